// round 12
// baseline (speedup 1.0000x reference)
#include <cuda_runtime.h>
#include <cstdint>

#define ROW_L 2048
#define S_OUT 65
#define OUT_PER_ROW 4225
#define ROWS_PER_TILE 4
#define NT 512

#define TILE_OUT_BYTES (OUT_PER_ROW * ROWS_PER_TILE * 4)   // 67600, multiple of 16

// SMEM layout (bytes)
#define OFF_BUF0   0
#define OFF_BUF1   TILE_OUT_BYTES                  // 67600
#define OFF_HEAD   (2 * TILE_OUT_BYTES)            // 135200 : 4 x 68 floats
#define OFF_XS     (OFF_HEAD + 1088)               // 136288 : 4 x 68 floats
#define OFF_RED    (OFF_XS + 1088)                 // 137376 : 16 x 2 doubles (8B aligned)
#define OFF_REDI   (OFF_RED + 256)                 // 137632 : 16 x 2 ints
#define OFF_STAT   (OFF_REDI + 128)                // 137760 : 4 x 2 floats
#define SMEM_TOTAL (OFF_STAT + 32)                 // 137792

__device__ __forceinline__ uint32_t s2u(const void* p) {
    return (uint32_t)__cvta_generic_to_shared(p);
}

__device__ __forceinline__ float thresh_val(float xi, float xj) {
    // 1.0f iff |xi-xj| < 0.2f else 0.0f; NaN -> 0.0f (sat(NaN)=+0).
    // 0.2f*2^100 exact; (0.2f-|d|) Sterbenz-exact near threshold -> sign bit-exact.
    const float BIG  = 0x1p100f;
    const float CBIG = 0.2f * 0x1p100f;
    return __saturatef(fmaf(fabsf(xi - xj), -BIG, CBIG));
}

__global__ __launch_bounds__(NT)
void rp_kernel(const float* __restrict__ x, float* __restrict__ out, int ntiles)
{
    extern __shared__ __align__(16) char smem[];
    float*  s_buf[2] = { (float*)(smem + OFF_BUF0), (float*)(smem + OFF_BUF1) };
    float  (*s_head)[68]  = (float(*)[68])(smem + OFF_HEAD);
    float  (*s_xs)[68]    = (float(*)[68])(smem + OFF_XS);
    double (*s_red)[2]    = (double(*)[2])(smem + OFF_RED);    // [g*4+wg]
    int    (*s_redi)[2]   = (int(*)[2])(smem + OFF_REDI);
    float  (*s_stat)[2]   = (float(*)[2])(smem + OFF_STAT);

    const int tid  = threadIdx.x;
    const int g    = tid >> 7;          // row-in-tile (0..3)
    const int t    = tid & 127;         // thread within row group
    const int wg   = (tid >> 5) & 3;    // warp within row group
    const int lane = tid & 31;

    int parity = 0;

    for (int tile = blockIdx.x; tile < ntiles; tile += gridDim.x) {
        float* so = s_buf[parity];

        const float* __restrict__ xr =
            x + ((size_t)tile * ROWS_PER_TILE + g) * ROW_L;

        // ---- load: 4 x LDG.128 per thread, front-batched ----
        float4 v[4];
#pragma unroll
        for (int k = 0; k < 4; k++)
            v[k] = __ldcs((const float4*)xr + k * 128 + t);

        // ensure prior tile's readers of head/xs/red are done before overwrite
        __syncthreads();

        if (t < 17) ((float4*)s_head[g])[t] = v[0];   // floats 0..67 of row

        // ---- per-thread fp32 pairwise sums + nonzero extent ----
        float s4[4], q4[4];
        int mn = ROW_L, mx = -1;
#pragma unroll
        for (int k = 0; k < 4; k++) {
            float4 a = v[k];
            s4[k] = (a.x + a.y) + (a.z + a.w);
            q4[k] = fmaf(a.x, a.x, fmaf(a.y, a.y, fmaf(a.z, a.z, a.w * a.w)));
            int base = (k * 128 + t) * 4;
            if (a.x != 0.f) { mn = min(mn, base    ); mx = max(mx, base    ); }
            if (a.y != 0.f) { mn = min(mn, base + 1); mx = max(mx, base + 1); }
            if (a.z != 0.f) { mn = min(mn, base + 2); mx = max(mx, base + 2); }
            if (a.w != 0.f) { mn = min(mn, base + 3); mx = max(mx, base + 3); }
        }
        float s8 = (s4[0] + s4[1]) + (s4[2] + s4[3]);
        float q8 = (q4[0] + q4[1]) + (q4[2] + q4[3]);

        // ---- fp64 warp shuffle tree (accuracy-preserving) ----
        double sd = (double)s8, qd = (double)q8;
#pragma unroll
        for (int off = 16; off; off >>= 1) {
            sd += __shfl_down_sync(0xffffffffu, sd, off);
            qd += __shfl_down_sync(0xffffffffu, qd, off);
            mn  = min(mn, __shfl_down_sync(0xffffffffu, mn, off));
            mx  = max(mx, __shfl_down_sync(0xffffffffu, mx, off));
        }
        if (lane == 0) {
            int w = g * 4 + wg;
            s_red[w][0]  = sd;  s_red[w][1]  = qd;
            s_redi[w][0] = mn;  s_redi[w][1] = mx;
        }
        __syncthreads();

        // ---- per-row stats (4 threads) ----
        if (tid < ROWS_PER_TILE) {
            int r = tid;
            double S = 0.0, Q = 0.0; int m1 = ROW_L, m2 = -1;
#pragma unroll
            for (int w = 0; w < 4; w++) {
                S += s_red[r * 4 + w][0];
                Q += s_red[r * 4 + w][1];
                m1 = min(m1, s_redi[r * 4 + w][0]);
                m2 = max(m2, s_redi[r * 4 + w][1]);
            }
            double cnt  = (m2 >= m1) ? (double)(m2 - m1 + 1) : 1.0;
            double mean = S / cnt;
            double var  = Q / cnt - mean * mean;
            if (var < 0.0) var = 0.0;
            s_stat[r][0] = (float)mean;
            s_stat[r][1] = fmaxf(sqrtf((float)var), 1e-6f);
            s_redi[r * 4][0] = m1;       // combined extent for normalize
            s_redi[r * 4][1] = m2;
        }
        __syncthreads();

        // ---- normalize first 65 per row; NaN sentinel outside valid window ----
        if (tid < ROWS_PER_TILE * S_OUT) {
            int r = tid / S_OUT;
            int i = tid - r * S_OUT;
            int m1 = s_redi[r * 4][0], m2 = s_redi[r * 4][1];
            bool valid = (m2 >= m1) && (i >= m1) && (i <= m2);
            s_xs[r][i] = valid ? (s_head[r][i] - s_stat[r][0]) / s_stat[r][1]
                               : __int_as_float(0x7fffffff);   // NaN
        }
        // before overwriting staging buffer: copy issued 2 tiles ago must be done
        if (tid == 0)
            asm volatile("cp.async.bulk.wait_group 1;" ::: "memory");
        __syncthreads();

        // ---- compute 65x65 per row into SMEM staging ----
        if (t < S_OUT) {
            float xi = s_xs[g][t];
            float* dst = so + g * OUT_PER_ROW + t * S_OUT;  // stride 65: conflict-free
            const float4* xs4 = (const float4*)s_xs[g];
#pragma unroll
            for (int jc = 0; jc < 16; jc++) {
                float4 b = xs4[jc];
                dst[jc * 4 + 0] = thresh_val(xi, b.x);
                dst[jc * 4 + 1] = thresh_val(xi, b.y);
                dst[jc * 4 + 2] = thresh_val(xi, b.z);
                dst[jc * 4 + 3] = thresh_val(xi, b.w);
            }
            dst[64] = thresh_val(xi, s_xs[g][64]);
        }
        __syncthreads();

        // ---- bulk async store: SMEM -> GMEM, drain overlaps next tile ----
        if (tid == 0) {
            asm volatile("fence.proxy.async.shared::cta;" ::: "memory");
            uint64_t gdst = (uint64_t)(out +
                (size_t)tile * (OUT_PER_ROW * ROWS_PER_TILE));
            asm volatile("cp.async.bulk.global.shared::cta.bulk_group [%0], [%1], %2;"
                         :: "l"(gdst), "r"(s2u(so)), "n"(TILE_OUT_BYTES) : "memory");
            asm volatile("cp.async.bulk.commit_group;" ::: "memory");
        }
        parity ^= 1;
    }

    // all outstanding copies must complete before CTA exit frees SMEM
    if (tid == 0)
        asm volatile("cp.async.bulk.wait_group 0;" ::: "memory");
}

extern "C" void kernel_launch(void* const* d_in, const int* in_sizes, int n_in,
                              void* d_out, int out_size)
{
    const float* x = (const float*)d_in[0];
    float* out = (float*)d_out;
    int rows   = in_sizes[0] / ROW_L;            // 16384
    int ntiles = rows / ROWS_PER_TILE;           // 4096

    int nsm = 148;
    cudaDeviceProp prop;
    if (cudaGetDeviceProperties(&prop, 0) == cudaSuccess)
        nsm = prop.multiProcessorCount;          // 152 on GB300

    cudaFuncSetAttribute(rp_kernel, cudaFuncAttributeMaxDynamicSharedMemorySize,
                         SMEM_TOTAL);
    rp_kernel<<<nsm, NT, SMEM_TOTAL>>>(x, out, ntiles);
}

// round 15
// speedup vs baseline: 1.3401x; 1.3401x over previous
#include <cuda_runtime.h>
#include <cstdint>

#define ROW_L 2048
#define S_OUT 65
#define OUT_PER_ROW 4225
#define ROWS_PER_CTA 4
#define NT 512

#define TILE_OUT_BYTES (OUT_PER_ROW * ROWS_PER_CTA * 4)   // 67600, multiple of 16

// SMEM layout (bytes)
#define OFF_BUF    0
#define OFF_HEAD   TILE_OUT_BYTES                  // 67600 (16-aligned): 4 x 68 floats
#define OFF_XS     (OFF_HEAD + 1088)               // 68688 : 4 x 68 floats
#define OFF_RED    (OFF_XS + 1088)                 // 69776 : 16 x 2 doubles
#define OFF_REDI   (OFF_RED + 256)                 // 70032 : 16 x 2 ints
#define OFF_STAT   (OFF_REDI + 128)                // 70160 : 4 x 2 floats
#define SMEM_TOTAL (OFF_STAT + 32)                 // 70192

__device__ __forceinline__ uint32_t s2u(const void* p) {
    return (uint32_t)__cvta_generic_to_shared(p);
}

__device__ __forceinline__ float thresh_val(float xi, float xj) {
    // 1.0f iff |xi-xj| < 0.2f else 0.0f; NaN -> 0.0f (sat(NaN)=+0).
    // 0.2f*2^100 exact; (0.2f-|d|) Sterbenz-exact near threshold -> sign bit-exact.
    const float BIG  = 0x1p100f;
    const float CBIG = 0.2f * 0x1p100f;
    return __saturatef(fmaf(fabsf(xi - xj), -BIG, CBIG));
}

__global__ __launch_bounds__(NT, 3)
void rp_kernel(const float* __restrict__ x, float* __restrict__ out)
{
    extern __shared__ __align__(16) char smem[];
    float*  s_out = (float*)(smem + OFF_BUF);
    float  (*s_head)[68]  = (float(*)[68])(smem + OFF_HEAD);
    float  (*s_xs)[68]    = (float(*)[68])(smem + OFF_XS);
    double (*s_red)[2]    = (double(*)[2])(smem + OFF_RED);    // [g*4+wg]
    int    (*s_redi)[2]   = (int(*)[2])(smem + OFF_REDI);
    float  (*s_stat)[2]   = (float(*)[2])(smem + OFF_STAT);

    const int tid  = threadIdx.x;
    const int g    = tid >> 7;          // row-in-tile (0..3)
    const int t    = tid & 127;         // thread within 128-thread row group
    const int wg   = (tid >> 5) & 3;    // warp within row group
    const int lane = tid & 31;

    const float* __restrict__ xr =
        x + ((size_t)blockIdx.x * ROWS_PER_CTA + g) * ROW_L;

    // ---- load: 4 x LDG.128 per thread, front-batched ----
    float4 v[4];
#pragma unroll
    for (int k = 0; k < 4; k++)
        v[k] = __ldcs((const float4*)xr + k * 128 + t);

    if (t < 17) ((float4*)s_head[g])[t] = v[0];   // floats 0..67 of row

    // ---- per-thread fp32 pairwise sums + nonzero extent ----
    float s4[4], q4[4];
    int mn = ROW_L, mx = -1;
#pragma unroll
    for (int k = 0; k < 4; k++) {
        float4 a = v[k];
        s4[k] = (a.x + a.y) + (a.z + a.w);
        q4[k] = fmaf(a.x, a.x, fmaf(a.y, a.y, fmaf(a.z, a.z, a.w * a.w)));
        int base = (k * 128 + t) * 4;
        if (a.x != 0.f) { mn = min(mn, base    ); mx = max(mx, base    ); }
        if (a.y != 0.f) { mn = min(mn, base + 1); mx = max(mx, base + 1); }
        if (a.z != 0.f) { mn = min(mn, base + 2); mx = max(mx, base + 2); }
        if (a.w != 0.f) { mn = min(mn, base + 3); mx = max(mx, base + 3); }
    }
    float s8 = (s4[0] + s4[1]) + (s4[2] + s4[3]);
    float q8 = (q4[0] + q4[1]) + (q4[2] + q4[3]);

    // ---- fp64 warp shuffle tree (accuracy-preserving) ----
    double sd = (double)s8, qd = (double)q8;
#pragma unroll
    for (int off = 16; off; off >>= 1) {
        sd += __shfl_down_sync(0xffffffffu, sd, off);
        qd += __shfl_down_sync(0xffffffffu, qd, off);
        mn  = min(mn, __shfl_down_sync(0xffffffffu, mn, off));
        mx  = max(mx, __shfl_down_sync(0xffffffffu, mx, off));
    }
    if (lane == 0) {
        int w = g * 4 + wg;
        s_red[w][0]  = sd;  s_red[w][1]  = qd;
        s_redi[w][0] = mn;  s_redi[w][1] = mx;
    }
    __syncthreads();

    // ---- per-row stats (4 threads) ----
    if (tid < ROWS_PER_CTA) {
        int r = tid;
        double S = 0.0, Q = 0.0; int m1 = ROW_L, m2 = -1;
#pragma unroll
        for (int w = 0; w < 4; w++) {
            S += s_red[r * 4 + w][0];
            Q += s_red[r * 4 + w][1];
            m1 = min(m1, s_redi[r * 4 + w][0]);
            m2 = max(m2, s_redi[r * 4 + w][1]);
        }
        double cnt  = (m2 >= m1) ? (double)(m2 - m1 + 1) : 1.0;
        double mean = S / cnt;
        double var  = Q / cnt - mean * mean;
        if (var < 0.0) var = 0.0;
        s_stat[r][0] = (float)mean;
        s_stat[r][1] = fmaxf(sqrtf((float)var), 1e-6f);
        s_redi[r * 4][0] = m1;       // combined extent for normalize
        s_redi[r * 4][1] = m2;
    }
    __syncthreads();

    // ---- normalize first 65 per row; NaN sentinel outside valid window ----
    if (tid < ROWS_PER_CTA * S_OUT) {
        int r = tid / S_OUT;
        int i = tid - r * S_OUT;
        int m1 = s_redi[r * 4][0], m2 = s_redi[r * 4][1];
        bool valid = (m2 >= m1) && (i >= m1) && (i <= m2);
        s_xs[r][i] = valid ? (s_head[r][i] - s_stat[r][0]) / s_stat[r][1]
                           : __int_as_float(0x7fffffff);   // NaN
    }
    __syncthreads();

    // ---- compute 65x65 per row into SMEM staging ----
    // thread (g, t<65): i-row t of tile-row g; stride-65 stores are conflict-free,
    // xs[j] chunks are warp-uniform LDS.128 broadcasts.
    if (t < S_OUT) {
        float xi = s_xs[g][t];
        float* dst = s_out + g * OUT_PER_ROW + t * S_OUT;
        const float4* xs4 = (const float4*)s_xs[g];
#pragma unroll
        for (int jc = 0; jc < 16; jc++) {
            float4 b = xs4[jc];
            dst[jc * 4 + 0] = thresh_val(xi, b.x);
            dst[jc * 4 + 1] = thresh_val(xi, b.y);
            dst[jc * 4 + 2] = thresh_val(xi, b.z);
            dst[jc * 4 + 3] = thresh_val(xi, b.w);
        }
        dst[64] = thresh_val(xi, s_xs[g][64]);
    }
    __syncthreads();

    // ---- bulk TMA store: SMEM -> GMEM; drain hidden by the other resident CTAs ----
    if (tid == 0) {
        asm volatile("fence.proxy.async.shared::cta;" ::: "memory");
        uint64_t gdst = (uint64_t)(out +
            (size_t)blockIdx.x * (OUT_PER_ROW * ROWS_PER_CTA));
        asm volatile("cp.async.bulk.global.shared::cta.bulk_group [%0], [%1], %2;"
                     :: "l"(gdst), "r"(s2u(s_out)), "n"(TILE_OUT_BYTES) : "memory");
        asm volatile("cp.async.bulk.commit_group;" ::: "memory");
        asm volatile("cp.async.bulk.wait_group 0;" ::: "memory");
    }
}

extern "C" void kernel_launch(void* const* d_in, const int* in_sizes, int n_in,
                              void* d_out, int out_size)
{
    const float* x = (const float*)d_in[0];
    float* out = (float*)d_out;
    int rows   = in_sizes[0] / ROW_L;            // 16384
    int blocks = rows / ROWS_PER_CTA;            // 4096

    cudaFuncSetAttribute(rp_kernel, cudaFuncAttributeMaxDynamicSharedMemorySize,
                         SMEM_TOTAL);
    rp_kernel<<<blocks, NT, SMEM_TOTAL>>>(x, out);
}